// round 12
// baseline (speedup 1.0000x reference)
#include <cuda_runtime.h>
#include <cuda_fp16.h>
#include <math.h>

#define LSEQ   8192
#define NFFT   16384      // 4^7
#define DMODEL 1024
#define ORDER  64
#define BANDS  16
#define EMB    33
#define FFT_THREADS 1024

// padded shared layout for data
#define PHYS(i) ((i) + ((i) >> 5))
#define SM_DATA 16896                       // >= PHYS(16383)+1
#define SMEM_BYTES (SM_DATA * sizeof(float2))

// rotation constants: exp(-i*pi*b/8)
#define RC8 0.9238795325112867f
#define RS8 0.3826834323650898f
#define RC4 0.7071067811865476f

// scratch (device globals; no cudaMalloc allowed)
__device__ float   g_h3[LSEQ * ORDER];       // 2 MB
__device__ float   g_k [DMODEL * LSEQ];      // 32 MB
__device__ __half2 g_kf[DMODEL * NFFT];      // 64 MB (plane-major digit-reversed, pre-scaled 1/N)

__device__ __forceinline__ float2 cmul(float2 a, float2 b) {
    return make_float2(fmaf(a.x, b.x, -a.y * b.y), fmaf(a.x, b.y, a.y * b.x));
}
__device__ __forceinline__ float2 conjf2(float2 a) { return make_float2(a.x, -a.y); }
__device__ __forceinline__ float2 cpow4(float2 z) { float2 z2 = cmul(z, z); return cmul(z2, z2); }

// exp(-2*pi*i*idx/NFFT), idx in [0, 4096): arg in (-pi/2, 0]
__device__ __forceinline__ float2 twgen(int idx) {
    float s, c;
    __sincosf((float)idx * -3.834951969714103e-4f, &s, &c);
    return make_float2(c, s);
}

__device__ __forceinline__ void bf4_fwd(float2& A, float2& B, float2& C, float2& D) {
    float2 t0 = make_float2(A.x + C.x, A.y + C.y);
    float2 t1 = make_float2(A.x - C.x, A.y - C.y);
    float2 t2 = make_float2(B.x + D.x, B.y + D.y);
    float2 t3 = make_float2(B.x - D.x, B.y - D.y);
    A = make_float2(t0.x + t2.x, t0.y + t2.y);
    B = make_float2(t1.x + t3.y, t1.y - t3.x);   // t1 - i*t3
    C = make_float2(t0.x - t2.x, t0.y - t2.y);
    D = make_float2(t1.x - t3.y, t1.y + t3.x);   // t1 + i*t3
}
__device__ __forceinline__ void bf4_inv(float2& A, float2& B, float2& C, float2& D) {
    float2 t0 = make_float2(A.x + C.x, A.y + C.y);
    float2 t1 = make_float2(A.x - C.x, A.y - C.y);
    float2 t2 = make_float2(B.x + D.x, B.y + D.y);
    float2 t3 = make_float2(B.x - D.x, B.y - D.y);
    A = make_float2(t0.x + t2.x, t0.y + t2.y);
    B = make_float2(t1.x - t3.y, t1.y + t3.x);   // t1 + i*t3
    C = make_float2(t0.x - t2.x, t0.y - t2.y);
    D = make_float2(t1.x + t3.y, t1.y - t3.x);   // t1 - i*t3
}

__device__ __forceinline__ void make_wb(float2 w0, float2* wb) {
    wb[0] = w0;
    wb[1] = cmul(w0, make_float2(RC8, -RS8));
    wb[2] = cmul(w0, make_float2(RC4, -RC4));
    wb[3] = cmul(w0, make_float2(RS8, -RC8));
}
__device__ __forceinline__ void make_wb_conj(float2 cb, float2* wb) {
    wb[0] = cb;
    wb[1] = cmul(cb, make_float2(RC8, RS8));
    wb[2] = cmul(cb, make_float2(RC4, RC4));
    wb[3] = cmul(cb, make_float2(RS8, RC8));
}

// Generic fused forward DIF stages (T, T+1), NORM layout in/out (per-thread in-place).
template<int T>
__device__ __forceinline__ void fwd_pass(float2* __restrict__ s, int j0, int g) {
    constexpr int q  = NFFT >> (2 * T + 2);
    constexpr int q4 = q >> 2;
    const int base = g * (q << 2) + j0;
    float2 x[4][4];
#pragma unroll
    for (int a = 0; a < 4; ++a)
#pragma unroll
        for (int b = 0; b < 4; ++b)
            x[a][b] = s[PHYS(base + a * q + b * q4)];
    const float2 w0 = twgen(j0 << (2 * T));
    float2 wb[4]; make_wb(w0, wb);
#pragma unroll
    for (int b = 0; b < 4; ++b) {
        bf4_fwd(x[0][b], x[1][b], x[2][b], x[3][b]);
        float2 w1 = wb[b], w2 = cmul(w1, w1), w3 = cmul(w2, w1);
        x[1][b] = cmul(x[1][b], w1);
        x[2][b] = cmul(x[2][b], w2);
        x[3][b] = cmul(x[3][b], w3);
    }
    {
        float2 w1 = cpow4(w0), w2 = cmul(w1, w1), w3 = cmul(w2, w1);
#pragma unroll
        for (int a = 0; a < 4; ++a) {
            bf4_fwd(x[a][0], x[a][1], x[a][2], x[a][3]);
            x[a][1] = cmul(x[a][1], w1);
            x[a][2] = cmul(x[a][2], w2);
            x[a][3] = cmul(x[a][3], w3);
        }
    }
#pragma unroll
    for (int a = 0; a < 4; ++a)
#pragma unroll
        for (int b = 0; b < 4; ++b)
            s[PHYS(base + a * q + b * q4)] = x[a][b];
}

// Forward stages (4,5): NORM reads, writes r-plane-permuted layout.
// write set != read set per thread -> barrier between load and store.
__device__ __forceinline__ void fwd_pass4_perm(float2* __restrict__ s, int j0, int g) {
    const int base = g * 64 + j0;       // e = base + a*16 + b*4, j0 in [0,4)
    float2 x[4][4];
#pragma unroll
    for (int a = 0; a < 4; ++a)
#pragma unroll
        for (int b = 0; b < 4; ++b)
            x[a][b] = s[PHYS(base + a * 16 + b * 4)];
    const float2 w0 = twgen(j0 << 8);
    float2 wb[4]; make_wb(w0, wb);
#pragma unroll
    for (int b = 0; b < 4; ++b) {
        bf4_fwd(x[0][b], x[1][b], x[2][b], x[3][b]);
        float2 w1 = wb[b], w2 = cmul(w1, w1), w3 = cmul(w2, w1);
        x[1][b] = cmul(x[1][b], w1);
        x[2][b] = cmul(x[2][b], w2);
        x[3][b] = cmul(x[3][b], w3);
    }
    {
        float2 w1 = cpow4(w0), w2 = cmul(w1, w1), w3 = cmul(w2, w1);
#pragma unroll
        for (int a = 0; a < 4; ++a) {
            bf4_fwd(x[a][0], x[a][1], x[a][2], x[a][3]);
            x[a][1] = cmul(x[a][1], w1);
            x[a][2] = cmul(x[a][2], w2);
            x[a][3] = cmul(x[a][3], w3);
        }
    }
    __syncthreads();                    // all reads done before permuted writes
    // e = g*64 + a*16 + b*4 + j0 -> plane r = e&3 = j0, m = e>>2 = g*16 + a*4 + b
    const int wbase = j0 * 4096 + g * 16;
#pragma unroll
    for (int a = 0; a < 4; ++a)
#pragma unroll
        for (int b = 0; b < 4; ++b)
            s[PHYS(wbase + a * 4 + b)] = x[a][b];
}

// Inverse stages (1,2): reads r-plane-permuted, writes NORM.
__device__ __forceinline__ void inv_pass1_perm(float2* __restrict__ s, int j0, int B) {
    float2 x[4][4];
    const int rbase = j0 * 4096 + B * 16;
#pragma unroll
    for (int a = 0; a < 4; ++a)
#pragma unroll
        for (int b = 0; b < 4; ++b)
            x[a][b] = s[PHYS(rbase + b * 4 + a)];
    const float2 cb = conjf2(twgen(j0 << 8));
    {
        float2 w1 = cpow4(cb), w2 = cmul(w1, w1), w3 = cmul(w2, w1);
#pragma unroll
        for (int b = 0; b < 4; ++b) {
            x[1][b] = cmul(x[1][b], w1);
            x[2][b] = cmul(x[2][b], w2);
            x[3][b] = cmul(x[3][b], w3);
            bf4_inv(x[0][b], x[1][b], x[2][b], x[3][b]);
        }
    }
    float2 wa[4]; make_wb_conj(cb, wa);
#pragma unroll
    for (int a = 0; a < 4; ++a) {
        float2 w1 = wa[a], w2 = cmul(w1, w1), w3 = cmul(w2, w1);
        x[a][1] = cmul(x[a][1], w1);
        x[a][2] = cmul(x[a][2], w2);
        x[a][3] = cmul(x[a][3], w3);
        bf4_inv(x[a][0], x[a][1], x[a][2], x[a][3]);
    }
    __syncthreads();                    // all reads done before NORM writes
    const int wbase = B * 64 + j0;
#pragma unroll
    for (int a = 0; a < 4; ++a)
#pragma unroll
        for (int b = 0; b < 4; ++b)
            s[PHYS(wbase + b * 16 + a * 4)] = x[a][b];
}

// Inverse stages (3,4): NORM in/out (per-thread in-place).
__device__ __forceinline__ void inv_pass3(float2* __restrict__ s, int j0, int B) {
    const int base = B * 1024 + j0;     // e = base + b*256 + a*64
    float2 x[4][4];
#pragma unroll
    for (int a = 0; a < 4; ++a)
#pragma unroll
        for (int b = 0; b < 4; ++b)
            x[a][b] = s[PHYS(base + b * 256 + a * 64)];
    const float2 cb = conjf2(twgen(j0 << 4));
    {
        float2 w1 = cpow4(cb), w2 = cmul(w1, w1), w3 = cmul(w2, w1);
#pragma unroll
        for (int b = 0; b < 4; ++b) {
            x[1][b] = cmul(x[1][b], w1);
            x[2][b] = cmul(x[2][b], w2);
            x[3][b] = cmul(x[3][b], w3);
            bf4_inv(x[0][b], x[1][b], x[2][b], x[3][b]);
        }
    }
    float2 wa[4]; make_wb_conj(cb, wa);
#pragma unroll
    for (int a = 0; a < 4; ++a) {
        float2 w1 = wa[a], w2 = cmul(w1, w1), w3 = cmul(w2, w1);
        x[a][1] = cmul(x[a][1], w1);
        x[a][2] = cmul(x[a][2], w2);
        x[a][3] = cmul(x[a][3], w3);
        bf4_inv(x[a][0], x[a][1], x[a][2], x[a][3]);
    }
#pragma unroll
    for (int a = 0; a < 4; ++a)
#pragma unroll
        for (int b = 0; b < 4; ++b)
            s[PHYS(base + b * 256 + a * 64)] = x[a][b];
}

// ---------------------------------------------------------------------------
// Filter MLP: 256 CTAs x 128 threads, 32 positions per CTA, __sinf activations
// (freq = 1, |args| small -> MUFU-accurate). Each thread: 16 output chains.
// ---------------------------------------------------------------------------
__global__ __launch_bounds__(128) void mlp_kernel(
        const float* __restrict__ W1, const float* __restrict__ b1,
        const float* __restrict__ fq,
        const float* __restrict__ W2, const float* __restrict__ b2,
        const float* __restrict__ W3, const float* __restrict__ b3) {
    __shared__ float sW[64 * 64];
    __shared__ float sA[32][65];
    __shared__ float sB[32][65];
    __shared__ float sBias[64];
    __shared__ float sFq[64];
    const int tid = threadIdx.x;
    const int l0  = blockIdx.x * 32;
    const int lo  = tid >> 2;          // position 0..31
    const int ob  = (tid & 3) * 16;    // output sub-block

    for (int i = tid; i < 32 * EMB; i += 128) {
        int r = i / EMB, c = i - r * EMB;
        int l = l0 + r;
        float v;
        if (c == 0) {
            v = (float)l / (float)(LSEQ - 1);
        } else {
            int j = (c <= BANDS) ? (c - 1) : (c - 1 - BANDS);
            float f = 1e-4f + (float)j * ((float)(BANDS - 1) - 1e-4f) / (float)(BANDS - 1);
            float w = 6.283185307179586f * (float)l / (float)LSEQ;
            float sv, cv;
            sincosf(f * w, &sv, &cv);
            v = (c <= BANDS) ? cv : -sv;
        }
        sA[r][c] = v;
    }
    if (tid < 64) { sFq[tid] = fq[tid]; sBias[tid] = b1[tid]; }
    for (int i = tid; i < EMB * 64; i += 128) sW[i] = W1[i];
    __syncthreads();

    float acc[16];
#pragma unroll
    for (int i = 0; i < 16; ++i) acc[i] = sBias[ob + i];
    for (int e = 0; e < EMB; ++e) {
        float hv = sA[lo][e];
#pragma unroll
        for (int i = 0; i < 16; ++i) acc[i] = fmaf(hv, sW[e * 64 + ob + i], acc[i]);
    }
#pragma unroll
    for (int i = 0; i < 16; ++i) sB[lo][ob + i] = __sinf(sFq[ob + i] * acc[i]);
    __syncthreads();

    if (tid < 64) sBias[tid] = b2[tid];
    for (int i = tid; i < 64 * 64; i += 128) sW[i] = W2[i];
    __syncthreads();
#pragma unroll
    for (int i = 0; i < 16; ++i) acc[i] = sBias[ob + i];
#pragma unroll 4
    for (int e = 0; e < 64; ++e) {
        float hv = sB[lo][e];
#pragma unroll
        for (int i = 0; i < 16; ++i) acc[i] = fmaf(hv, sW[e * 64 + ob + i], acc[i]);
    }
#pragma unroll
    for (int i = 0; i < 16; ++i) sA[lo][ob + i] = __sinf(sFq[ob + i] * acc[i]);
    __syncthreads();

    if (tid < 64) sBias[tid] = b3[tid];
    for (int i = tid; i < 64 * 64; i += 128) sW[i] = W3[i];
    __syncthreads();
#pragma unroll
    for (int i = 0; i < 16; ++i) acc[i] = sBias[ob + i];
#pragma unroll 4
    for (int e = 0; e < 64; ++e) {
        float hv = sA[lo][e];
#pragma unroll
        for (int i = 0; i < 16; ++i) acc[i] = fmaf(hv, sW[e * 64 + ob + i], acc[i]);
    }
    float* outp = &g_h3[(l0 + lo) * 64 + ob];
#pragma unroll
    for (int i = 0; i < 16; ++i) outp[i] = __sinf(sFq[ob + i] * acc[i]);
}

// ---------------------------------------------------------------------------
// Output projection + exponential modulation -> g_k[d][l]
// ---------------------------------------------------------------------------
__global__ void proj_kernel(const float* __restrict__ Wout) {
    __shared__ float hs[64][ORDER + 1];
    __shared__ float ws[ORDER][64];
    const int l0 = blockIdx.x * 64;
    const int d0 = blockIdx.y * 64;
    const int tid = threadIdx.x;

    for (int i = tid; i < 64 * ORDER; i += 256) {
        int r = i >> 6, c = i & 63;
        hs[r][c] = g_h3[(l0 + r) * ORDER + c];
        ws[r][c] = __ldg(&Wout[r * DMODEL + d0 + c]);
    }
    __syncthreads();

    const int tl = tid & 15;
    const int td = tid >> 4;
    float acc[4][4];
#pragma unroll
    for (int j = 0; j < 4; ++j)
#pragma unroll
        for (int i = 0; i < 4; ++i) acc[j][i] = 0.f;

#pragma unroll 8
    for (int k = 0; k < ORDER; ++k) {
        float a0 = hs[tl * 4 + 0][k];
        float a1 = hs[tl * 4 + 1][k];
        float a2 = hs[tl * 4 + 2][k];
        float a3 = hs[tl * 4 + 3][k];
        float4 b = *(const float4*)&ws[k][td * 4];
        acc[0][0] = fmaf(a0, b.x, acc[0][0]); acc[0][1] = fmaf(a1, b.x, acc[0][1]);
        acc[0][2] = fmaf(a2, b.x, acc[0][2]); acc[0][3] = fmaf(a3, b.x, acc[0][3]);
        acc[1][0] = fmaf(a0, b.y, acc[1][0]); acc[1][1] = fmaf(a1, b.y, acc[1][1]);
        acc[1][2] = fmaf(a2, b.y, acc[1][2]); acc[1][3] = fmaf(a3, b.y, acc[1][3]);
        acc[2][0] = fmaf(a0, b.z, acc[2][0]); acc[2][1] = fmaf(a1, b.z, acc[2][1]);
        acc[2][2] = fmaf(a2, b.z, acc[2][2]); acc[2][3] = fmaf(a3, b.z, acc[2][3]);
        acc[3][0] = fmaf(a0, b.w, acc[3][0]); acc[3][1] = fmaf(a1, b.w, acc[3][1]);
        acc[3][2] = fmaf(a2, b.w, acc[3][2]); acc[3][3] = fmaf(a3, b.w, acc[3][3]);
    }

    const float dmin  = -3.0701134573253944f;
    const float dmax  = -15.350567286626972f;
    const float dstep = (dmax - dmin) / (float)(DMODEL - 1);
    float tvec[4];
#pragma unroll
    for (int i = 0; i < 4; ++i)
        tvec[i] = (float)(l0 + tl * 4 + i) / (float)(LSEQ - 1);

#pragma unroll
    for (int j = 0; j < 4; ++j) {
        int d = d0 + td * 4 + j;
        float delta = fabsf(dmin + dstep * (float)d);
        float4 v;
        v.x = acc[j][0] * __expf(-tvec[0] * delta);
        v.y = acc[j][1] * __expf(-tvec[1] * delta);
        v.z = acc[j][2] * __expf(-tvec[2] * delta);
        v.w = acc[j][3] * __expf(-tvec[3] * delta);
        *(float4*)&g_k[d * LSEQ + l0 + tl * 4] = v;
    }
}

// ---------------------------------------------------------------------------
// K spectrum -> fp16 gmem (plane-major, pre-scaled by 1/N)
// ---------------------------------------------------------------------------
__global__ void __launch_bounds__(FFT_THREADS, 1) fftk_kernel() {
    extern __shared__ float2 s[];
    const int d = blockIdx.x;
    const int tid = threadIdx.x;
    const float* kp = &g_k[d * LSEQ];

    // fused load + DIF stages (0,1): real input, zero-padded top half
    {
        const int j0 = tid;
        float2 x[4][4];
        const float2 w0 = twgen(j0);
        float2 wb[4]; make_wb(w0, wb);
#pragma unroll
        for (int b = 0; b < 4; ++b) {
            float A = kp[b * 1024 + j0];
            float B = kp[4096 + b * 1024 + j0];
            float2 u0 = make_float2(A + B, 0.f);
            float2 u1 = make_float2(A, -B);          // A - i*B
            float2 u2 = make_float2(A - B, 0.f);
            float2 u3 = make_float2(A, B);           // A + i*B
            float2 w1 = wb[b], w2 = cmul(w1, w1), w3 = cmul(w2, w1);
            x[0][b] = u0;
            x[1][b] = cmul(u1, w1);
            x[2][b] = cmul(u2, w2);
            x[3][b] = cmul(u3, w3);
        }
        float2 w1 = cpow4(w0), w2 = cmul(w1, w1), w3 = cmul(w2, w1);
#pragma unroll
        for (int a = 0; a < 4; ++a) {
            bf4_fwd(x[a][0], x[a][1], x[a][2], x[a][3]);
            x[a][1] = cmul(x[a][1], w1);
            x[a][2] = cmul(x[a][2], w2);
            x[a][3] = cmul(x[a][3], w3);
        }
#pragma unroll
        for (int a = 0; a < 4; ++a)
#pragma unroll
            for (int b = 0; b < 4; ++b)
                s[PHYS(a * 4096 + b * 1024 + j0)] = x[a][b];
    }
    __syncthreads();
    fwd_pass<2>(s, tid & 63, tid >> 6);
    __syncthreads();
    fwd_pass4_perm(s, tid >> 8, tid & 255);
    __syncthreads();

    __half2* kf = &g_kf[d * NFFT];
    const float sc = 1.0f / (float)NFFT;
#pragma unroll
    for (int it = 0; it < 4; ++it) {
        int m = it * FFT_THREADS + tid;
        float2 A = s[PHYS(0 * 4096 + m)];
        float2 B = s[PHYS(1 * 4096 + m)];
        float2 C = s[PHYS(2 * 4096 + m)];
        float2 D = s[PHYS(3 * 4096 + m)];
        bf4_fwd(A, B, C, D);
        kf[0 * 4096 + m] = __floats2half2_rn(A.x * sc, A.y * sc);
        kf[1 * 4096 + m] = __floats2half2_rn(B.x * sc, B.y * sc);
        kf[2 * 4096 + m] = __floats2half2_rn(C.x * sc, C.y * sc);
        kf[3 * 4096 + m] = __floats2half2_rn(D.x * sc, D.y * sc);
    }
}

// ---------------------------------------------------------------------------
// Convolution
// ---------------------------------------------------------------------------
__global__ void __launch_bounds__(FFT_THREADS, 1)
conv_kernel(const float* __restrict__ x, const float* __restrict__ Dv,
            float* __restrict__ out) {
    extern __shared__ float2 s[];
    const int d = blockIdx.x;
    const int tid = threadIdx.x;
    const float* x0 = x + d * LSEQ;
    const float* x1 = x + (DMODEL + d) * LSEQ;

    // fused load + DIF stages (0,1): a=2,3 legs are zero (padding)
    {
        const int j0 = tid;
        float2 x4[4][4];
        const float2 w0 = twgen(j0);
        float2 wb[4]; make_wb(w0, wb);
#pragma unroll
        for (int b = 0; b < 4; ++b) {
            int e0 = b * 1024 + j0;
            float2 A = make_float2(x0[e0], x1[e0]);
            float2 B = make_float2(x0[e0 + 4096], x1[e0 + 4096]);
            float2 u0 = make_float2(A.x + B.x, A.y + B.y);
            float2 u1 = make_float2(A.x + B.y, A.y - B.x);   // A - i*B
            float2 u2 = make_float2(A.x - B.x, A.y - B.y);
            float2 u3 = make_float2(A.x - B.y, A.y + B.x);   // A + i*B
            float2 w1 = wb[b], w2 = cmul(w1, w1), w3 = cmul(w2, w1);
            x4[0][b] = u0;
            x4[1][b] = cmul(u1, w1);
            x4[2][b] = cmul(u2, w2);
            x4[3][b] = cmul(u3, w3);
        }
        float2 w1 = cpow4(w0), w2 = cmul(w1, w1), w3 = cmul(w2, w1);
#pragma unroll
        for (int a = 0; a < 4; ++a) {
            bf4_fwd(x4[a][0], x4[a][1], x4[a][2], x4[a][3]);
            x4[a][1] = cmul(x4[a][1], w1);
            x4[a][2] = cmul(x4[a][2], w2);
            x4[a][3] = cmul(x4[a][3], w3);
        }
#pragma unroll
        for (int a = 0; a < 4; ++a)
#pragma unroll
            for (int b = 0; b < 4; ++b)
                s[PHYS(a * 4096 + b * 1024 + j0)] = x4[a][b];
    }
    __syncthreads();
    fwd_pass<2>(s, tid & 63, tid >> 6);
    __syncthreads();
    fwd_pass4_perm(s, tid >> 8, tid & 255);
    __syncthreads();

    // mid: DIF stage 6 + pointwise * K_f(fp16 gmem) + DIT stage 0 (stride-1)
    const __half2* kf = &g_kf[d * NFFT];
#pragma unroll
    for (int it = 0; it < 4; ++it) {
        int m = it * FFT_THREADS + tid;
        float2 A = s[PHYS(0 * 4096 + m)];
        float2 B = s[PHYS(1 * 4096 + m)];
        float2 C = s[PHYS(2 * 4096 + m)];
        float2 D = s[PHYS(3 * 4096 + m)];
        bf4_fwd(A, B, C, D);
        A = cmul(A, __half22float2(__ldg(&kf[0 * 4096 + m])));
        B = cmul(B, __half22float2(__ldg(&kf[1 * 4096 + m])));
        C = cmul(C, __half22float2(__ldg(&kf[2 * 4096 + m])));
        D = cmul(D, __half22float2(__ldg(&kf[3 * 4096 + m])));
        bf4_inv(A, B, C, D);
        s[PHYS(0 * 4096 + m)] = A;
        s[PHYS(1 * 4096 + m)] = B;
        s[PHYS(2 * 4096 + m)] = C;
        s[PHYS(3 * 4096 + m)] = D;
    }
    __syncthreads();

    inv_pass1_perm(s, tid >> 8, tid & 255);
    __syncthreads();
    inv_pass3(s, tid & 63, tid >> 6);
    __syncthreads();

    // final inverse stages (5,6) fused with gmem store (+ skip connection)
    {
        const int j0 = tid;
        float2 xx[4][4];
#pragma unroll
        for (int a = 0; a < 4; ++a)
#pragma unroll
            for (int b = 0; b < 4; ++b)
                xx[a][b] = s[PHYS(b * 4096 + a * 1024 + j0)];
        const float2 cb = conjf2(twgen(j0));
        {
            float2 w1 = cpow4(cb), w2 = cmul(w1, w1), w3 = cmul(w2, w1);
#pragma unroll
            for (int b = 0; b < 4; ++b) {
                xx[1][b] = cmul(xx[1][b], w1);
                xx[2][b] = cmul(xx[2][b], w2);
                xx[3][b] = cmul(xx[3][b], w3);
                bf4_inv(xx[0][b], xx[1][b], xx[2][b], xx[3][b]);
            }
        }
        float2 wa[4]; make_wb_conj(cb, wa);
#pragma unroll
        for (int a = 0; a < 4; ++a) {
            float2 w1 = wa[a], w2 = cmul(w1, w1), w3 = cmul(w2, w1);
            xx[a][1] = cmul(xx[a][1], w1);
            xx[a][2] = cmul(xx[a][2], w2);
            xx[a][3] = cmul(xx[a][3], w3);
            bf4_inv(xx[a][0], xx[a][1], xx[a][2], xx[a][3]);
        }
        const float Dd = __ldg(&Dv[d]);
        float* o0 = out + d * LSEQ;
        float* o1 = out + (DMODEL + d) * LSEQ;
#pragma unroll
        for (int b = 0; b < 2; ++b)
#pragma unroll
            for (int a = 0; a < 4; ++a) {
                int e = b * 4096 + a * 1024 + j0;
                o0[e] = fmaf(x0[e], Dd, xx[a][b].x);
                o1[e] = fmaf(x1[e], Dd, xx[a][b].y);
            }
    }
}

// ---------------------------------------------------------------------------
extern "C" void kernel_launch(void* const* d_in, const int* in_sizes, int n_in,
                              void* d_out, int out_size) {
    const float* x    = (const float*)d_in[0];
    const float* W1   = (const float*)d_in[2];
    const float* b1   = (const float*)d_in[3];
    const float* fq   = (const float*)d_in[4];
    const float* W2   = (const float*)d_in[5];
    const float* b2   = (const float*)d_in[6];
    const float* W3   = (const float*)d_in[7];
    const float* b3   = (const float*)d_in[8];
    const float* Wout = (const float*)d_in[9];
    const float* Dv   = (const float*)d_in[10];
    float* out = (float*)d_out;
    (void)in_sizes; (void)n_in; (void)out_size;

    cudaFuncSetAttribute(fftk_kernel, cudaFuncAttributeMaxDynamicSharedMemorySize, (int)SMEM_BYTES);
    cudaFuncSetAttribute(conv_kernel, cudaFuncAttributeMaxDynamicSharedMemorySize, (int)SMEM_BYTES);

    mlp_kernel<<<LSEQ / 32, 128>>>(W1, b1, fq, W2, b2, W3, b3);
    proj_kernel<<<dim3(LSEQ / 64, DMODEL / 64), 256>>>(Wout);
    fftk_kernel<<<DMODEL, FFT_THREADS, SMEM_BYTES>>>();
    conv_kernel<<<DMODEL, FFT_THREADS, SMEM_BYTES>>>(x, Dv, out);
}